// round 1
// baseline (speedup 1.0000x reference)
#include <cuda_runtime.h>
#include <cstdint>

// Problem constants
static constexpr int Bb = 8;
static constexpr int Nn = 2048;
static constexpr int Mm = 3072;
static constexpr int FEe = 64;
static constexpr int Dd = 128;

// Output layout (flattened tuple: H_new, E_new, Hm, alpha, beta), float32
static constexpr size_t OFF_H     = 0;
static constexpr size_t OFF_E     = (size_t)Bb * Nn * Dd;                    // 2,097,152
static constexpr size_t OFF_HM    = OFF_E + (size_t)Bb * Mm * Dd;            // 5,242,880
static constexpr size_t OFF_ALPHA = OFF_HM + (size_t)Bb * Nn * Dd;           // 7,340,032
static constexpr size_t OFF_BETA  = OFF_ALPHA + (size_t)Bb * Nn * Nn;        // 40,894,464

// Scratch (__device__ globals: no allocation allowed)
__device__ float g_Et[(size_t)Bb * Mm * Dd];     // E_t, fp32, 12.6 MB
__device__ float g_t1[Bb * Mm];                  // E_t . b1
__device__ float g_t2[Bb * Mm];                  // E_t . b2
__device__ float g_ecpart[Bb * 24 * Dd];         // partial column sums of E_t (deterministic reduction)
__device__ float g_scal[2 + 3 * Bb];             // [c1, c2, s3[8], ec0[8], gsh[8]]

// ---------------------------------------------------------------------------
// Block-wide sum over 256 threads (all threads must call; returns same value
// on every thread; safe to call repeatedly with the same sred buffer).
// ---------------------------------------------------------------------------
__device__ __forceinline__ float bredSum256(float v, float* sred) {
    #pragma unroll
    for (int o = 16; o; o >>= 1) v += __shfl_down_sync(0xffffffffu, v, o);
    __syncthreads();
    if ((threadIdx.x & 31) == 0) sred[threadIdx.x >> 5] = v;
    __syncthreads();
    float t = 0.f;
    #pragma unroll
    for (int k = 0; k < 8; k++) t += sred[k];
    return t;
}

// exp(tanh(x)) with tanh(x) = 1 - 2/(exp(2x)+1)  (3 MUFU ops total)
__device__ __forceinline__ float exp_tanh(float x) {
    float ez = __expf(2.0f * x);
    float t  = 1.0f - __fdividef(2.0f, ez + 1.0f);
    return __expf(t);
}

// ---------------------------------------------------------------------------
// Kernel 1: E_t = link_features @ WE ; t1 = E_t.b1 ; t2 = E_t.b2
// 128 threads, 16 rows per CTA.  grid = B*M/16 = 1536
// ---------------------------------------------------------------------------
__global__ __launch_bounds__(128) void k_et(const float* __restrict__ link,
                                            const float* __restrict__ Wmat,
                                            const float* __restrict__ bvec) {
    __shared__ float sWE[FEe][Dd];      // 32 KB
    __shared__ float sLink[16][FEe];    // 4 KB
    __shared__ float sP1[16][4];
    __shared__ float sP2[16][4];

    const int tid = threadIdx.x;                  // 0..127 == d
    const int rowBase = blockIdx.x * 16;          // global edge row

    for (int i = tid; i < FEe * Dd; i += 128) sWE[i >> 7][i & 127] = Wmat[i];
    for (int i = tid; i < 16 * FEe; i += 128) {
        int r = i >> 6, f = i & 63;
        sLink[r][f] = link[(size_t)(rowBase + r) * FEe + f];
    }
    __syncthreads();

    const float b1v = bvec[tid];
    const float b2v = bvec[Dd + tid];
    const int lane = tid & 31, warp = tid >> 5;

    #pragma unroll 1
    for (int r = 0; r < 16; r++) {
        float acc = 0.f;
        #pragma unroll
        for (int f = 0; f < FEe; f++) acc = fmaf(sLink[r][f], sWE[f][tid], acc);
        g_Et[(size_t)(rowBase + r) * Dd + tid] = acc;
        float p1 = acc * b1v, p2 = acc * b2v;
        #pragma unroll
        for (int o = 16; o; o >>= 1) {
            p1 += __shfl_down_sync(0xffffffffu, p1, o);
            p2 += __shfl_down_sync(0xffffffffu, p2, o);
        }
        if (lane == 0) { sP1[r][warp] = p1; sP2[r][warp] = p2; }
    }
    __syncthreads();
    if (tid < 16) {
        g_t1[rowBase + tid] = sP1[tid][0] + sP1[tid][1] + sP1[tid][2] + sP1[tid][3];
        g_t2[rowBase + tid] = sP2[tid][0] + sP2[tid][1] + sP2[tid][2] + sP2[tid][3];
    }
}

// ---------------------------------------------------------------------------
// Kernel 2: deterministic partial column sums of E_t (for ec)
// grid = B*24, block = 128 (thread = d). Each block sums 128 rows.
// ---------------------------------------------------------------------------
__global__ __launch_bounds__(128) void k_ec() {
    const int bx = blockIdx.x;
    const int b = bx / 24, seg = bx % 24;
    const int d = threadIdx.x;
    const float* p = g_Et + ((size_t)b * Mm + (size_t)seg * 128) * Dd + d;
    float acc = 0.f;
    #pragma unroll 4
    for (int m = 0; m < 128; m++) acc += p[(size_t)m * Dd];
    g_ecpart[(size_t)bx * Dd + d] = acc;
}

// ---------------------------------------------------------------------------
// Kernel 3: tiny scalar setup. 1 block of 256 threads.
//   c1 = WH.a1, c2 = WH.a2, s3[b] = ec.a3, ec0[b] = ec[b,0], gsh[b]=b3*h_avg[b]
// ---------------------------------------------------------------------------
__global__ __launch_bounds__(256) void k_scal(const float* __restrict__ bet,
                                              const float* __restrict__ WH,
                                              const float* __restrict__ av,
                                              const float* __restrict__ bv) {
    __shared__ float sred[8];
    const int tid = threadIdx.x;
    const float wh = (tid < Dd) ? WH[tid] : 0.f;
    float c1 = bredSum256(wh * ((tid < Dd) ? av[tid] : 0.f), sred);
    float c2 = bredSum256(wh * ((tid < Dd) ? av[Dd + tid] : 0.f), sred);
    if (tid == 0) { g_scal[0] = c1; g_scal[1] = c2; }

    const float invM = 1.0f / (float)Mm;
    for (int b = 0; b < Bb; b++) {
        float ecsum = 0.f;
        if (tid < Dd) {
            #pragma unroll
            for (int k = 0; k < 24; k++) ecsum += g_ecpart[(size_t)(b * 24 + k) * Dd + tid];
        }
        float ecv = ecsum * invM;
        float s3 = bredSum256(ecv * ((tid < Dd) ? av[2 * Dd + tid] : 0.f), sred);
        float h = 0.f;
        for (int i = tid; i < Nn; i += 256) h += bet[(size_t)b * Nn + i];
        float havg = bredSum256(h, sred) * (1.0f / (float)Nn);
        if (tid == 0) {
            g_scal[2 + b] = s3;
            float e0 = 0.f;
            for (int k = 0; k < 24; k++) e0 += g_ecpart[(size_t)(b * 24 + k) * Dd];
            g_scal[10 + b] = e0 * invM;         // ec[b,0]
            g_scal[18 + b] = bv[2 * Dd] * havg; // b3 * h_avg
        }
        __syncthreads();
    }
}

// ---------------------------------------------------------------------------
// Kernel 4: node attention. One CTA per (b,i) row.  grid = B*N = 16384, 256 thr
// w_j = adj ? exp(tanh(bet_i*c1 + bet_j*c2 + s3)) : 0 ; alpha = w/sum
// H_new[i,:] = (sum_j alpha_ij*bet_j)*WH ; Hm = ec0 * H_new
// ---------------------------------------------------------------------------
__global__ __launch_bounds__(256) void k_node(const float* __restrict__ bet,
                                              const int* __restrict__ adj,
                                              const float* __restrict__ WH,
                                              float* __restrict__ out) {
    __shared__ float sb[Nn];    // betweenness row (8 KB)
    __shared__ float sw[Nn];    // weights (8 KB)
    __shared__ float sred[8];

    const int row = blockIdx.x;
    const int b = row >> 11;            // / 2048
    const int i = row & (Nn - 1);
    const int tid = threadIdx.x;

    const float c1 = g_scal[0], c2 = g_scal[1];
    const float s3 = g_scal[2 + b], ec0 = g_scal[10 + b];

    const float* betb = bet + (size_t)b * Nn;
    for (int j = tid; j < Nn; j += 256) sb[j] = betb[j];
    __syncthreads();

    const float u = fmaf(sb[i], c1, s3);
    const int* ar = adj + (size_t)row * Nn;

    float lsum = 0.f;
    #pragma unroll 1
    for (int j = tid; j < Nn; j += 256) {
        float w = 0.f;
        if (ar[j] > 0) w = exp_tanh(fmaf(sb[j], c2, u));
        sw[j] = w;
        lsum += w;
    }
    float total = bredSum256(lsum, sred);
    const bool uni = !(total > 0.f);
    const float inv = uni ? 0.f : __fdividef(1.f, total);

    float* alphar = out + OFF_ALPHA + (size_t)row * Nn;
    float sacc = 0.f;
    #pragma unroll 1
    for (int j = tid; j < Nn; j += 256) {
        float aj = uni ? (1.0f / (float)Nn) : sw[j] * inv;
        alphar[j] = aj;
        sacc = fmaf(aj, sb[j], sacc);
    }
    float s = bredSum256(sacc, sred);

    if (tid < Dd) {
        float hv = s * WH[tid];
        out[OFF_H  + (size_t)row * Dd + tid] = hv;
        out[OFF_HM + (size_t)row * Dd + tid] = hv * ec0;
    }
}

// ---------------------------------------------------------------------------
// Kernel 5: edge attention softmax. One CTA per (b,i).  grid = B*M = 24576
// ---------------------------------------------------------------------------
__global__ __launch_bounds__(256) void k_edge(const int* __restrict__ adj,
                                              float* __restrict__ out) {
    __shared__ float st2[Mm];   // 12 KB
    __shared__ float sw[Mm];    // 12 KB
    __shared__ float sred[8];

    const int row = blockIdx.x;
    const int b = row / Mm;
    const int tid = threadIdx.x;

    const float gsh = g_scal[18 + b];
    const float* t2b = g_t2 + (size_t)b * Mm;
    for (int j = tid; j < Mm; j += 256) st2[j] = t2b[j];
    __syncthreads();

    const float u = g_t1[row] + gsh;
    const int* ar = adj + (size_t)row * Mm;

    float lsum = 0.f;
    #pragma unroll 1
    for (int j = tid; j < Mm; j += 256) {
        float w = 0.f;
        if (ar[j] > 0) w = exp_tanh(u + st2[j]);
        sw[j] = w;
        lsum += w;
    }
    float total = bredSum256(lsum, sred);
    const bool uni = !(total > 0.f);
    const float inv = uni ? 0.f : __fdividef(1.f, total);

    float* br = out + OFF_BETA + (size_t)row * Mm;
    #pragma unroll 1
    for (int j = tid; j < Mm; j += 256) {
        br[j] = uni ? (1.0f / (float)Mm) : sw[j] * inv;
    }
}

// ---------------------------------------------------------------------------
// Kernel 6: E_new = beta @ E_t  (per batch: [3072,3072]@[3072,128])
// BM=64 rows, BN=128 (all of D), BK=16. 128 threads, 8x8 register tile,
// packed fma.rn.f32x2 (2 FMA/instr).  grid = 48 tiles * 8 batches = 384
// ---------------------------------------------------------------------------
__global__ __launch_bounds__(128) void k_gemm(float* __restrict__ out) {
    constexpr int BM = 64, BK = 16;
    __shared__ float As[BK][BM + 4];   // beta tile, transposed
    __shared__ float Bs[BK][Dd];       // E_t tile

    const int tid = threadIdx.x;             // 128
    const int bm = blockIdx.x % 48;
    const int b  = blockIdx.x / 48;
    const int tx = tid & 15;                 // col group: tx*8
    const int ty = tid >> 4;                 // row group: ty*8

    const float* betab = out + OFF_BETA + (size_t)b * Mm * Mm + (size_t)bm * BM * Mm;
    const float* Etb   = g_Et + (size_t)b * Mm * Dd;

    unsigned long long acc[8][4];
    #pragma unroll
    for (int m = 0; m < 8; m++)
        #pragma unroll
        for (int p = 0; p < 4; p++) acc[m][p] = 0ull;

    #pragma unroll 1
    for (int k0 = 0; k0 < Mm; k0 += BK) {
        // beta tile: 64 rows x 16 k = 256 float4; 2 per thread
        #pragma unroll
        for (int t = 0; t < 2; t++) {
            int idx = tid + t * 128;
            int r = idx >> 2, k4 = (idx & 3) * 4;
            float4 v = *(const float4*)(betab + (size_t)r * Mm + k0 + k4);
            As[k4 + 0][r] = v.x; As[k4 + 1][r] = v.y;
            As[k4 + 2][r] = v.z; As[k4 + 3][r] = v.w;
        }
        // E_t tile: 16 rows x 128 d = 512 float4; 4 per thread
        #pragma unroll
        for (int t = 0; t < 4; t++) {
            int idx = tid + t * 128;
            int r = idx >> 5, d4 = (idx & 31) * 4;
            *(float4*)&Bs[r][d4] = *(const float4*)(Etb + (size_t)(k0 + r) * Dd + d4);
        }
        __syncthreads();

        #pragma unroll
        for (int kk = 0; kk < BK; kk++) {
            float a[8];
            *(float4*)&a[0] = *(const float4*)&As[kk][ty * 8];
            *(float4*)&a[4] = *(const float4*)&As[kk][ty * 8 + 4];
            unsigned long long bv[4];
            const unsigned long long* bp = (const unsigned long long*)&Bs[kk][tx * 8];
            bv[0] = bp[0]; bv[1] = bp[1]; bv[2] = bp[2]; bv[3] = bp[3];
            #pragma unroll
            for (int m = 0; m < 8; m++) {
                unsigned long long a2;
                asm("mov.b64 %0, {%1, %1};" : "=l"(a2) : "r"(__float_as_uint(a[m])));
                #pragma unroll
                for (int p = 0; p < 4; p++)
                    asm("fma.rn.f32x2 %0, %1, %2, %0;"
                        : "+l"(acc[m][p]) : "l"(a2), "l"(bv[p]));
            }
        }
        __syncthreads();
    }

    float* Cb = out + OFF_E + (size_t)b * Mm * Dd + (size_t)bm * BM * Dd;
    #pragma unroll
    for (int m = 0; m < 8; m++) {
        int r = ty * 8 + m;
        float4 o0, o1;
        o0.x = __uint_as_float((unsigned)acc[m][0]);
        o0.y = __uint_as_float((unsigned)(acc[m][0] >> 32));
        o0.z = __uint_as_float((unsigned)acc[m][1]);
        o0.w = __uint_as_float((unsigned)(acc[m][1] >> 32));
        o1.x = __uint_as_float((unsigned)acc[m][2]);
        o1.y = __uint_as_float((unsigned)(acc[m][2] >> 32));
        o1.z = __uint_as_float((unsigned)acc[m][3]);
        o1.w = __uint_as_float((unsigned)(acc[m][3] >> 32));
        *(float4*)(Cb + (size_t)r * Dd + tx * 8)     = o0;
        *(float4*)(Cb + (size_t)r * Dd + tx * 8 + 4) = o1;
    }
}

// ---------------------------------------------------------------------------
extern "C" void kernel_launch(void* const* d_in, const int* in_sizes, int n_in,
                              void* d_out, int out_size) {
    const float* bet  = (const float*)d_in[0];
    const float* link = (const float*)d_in[1];
    const int*   nadj = (const int*)d_in[2];
    const int*   eadj = (const int*)d_in[3];
    const float* WH   = (const float*)d_in[4];
    const float* WE   = (const float*)d_in[5];
    const float* av   = (const float*)d_in[6];
    const float* bv   = (const float*)d_in[7];
    float* out = (float*)d_out;

    k_et  <<<Bb * Mm / 16, 128>>>(link, WE, bv);
    k_ec  <<<Bb * 24, 128>>>();
    k_scal<<<1, 256>>>(bet, WH, av, bv);
    k_node<<<Bb * Nn, 256>>>(bet, nadj, WH, out);
    k_edge<<<Bb * Mm, 256>>>(eadj, out);
    k_gemm<<<48 * Bb, 128>>>(out);
}

// round 7
// speedup vs baseline: 1.9512x; 1.9512x over previous
#include <cuda_runtime.h>
#include <cstdint>

// Problem constants
static constexpr int Bb = 8;
static constexpr int Nn = 2048;
static constexpr int Mm = 3072;
static constexpr int FEe = 64;
static constexpr int Dd = 128;

// Output layout (flattened tuple: H_new, E_new, Hm, alpha, beta), float32
static constexpr size_t OFF_H     = 0;
static constexpr size_t OFF_E     = (size_t)Bb * Nn * Dd;
static constexpr size_t OFF_HM    = OFF_E + (size_t)Bb * Mm * Dd;
static constexpr size_t OFF_ALPHA = OFF_HM + (size_t)Bb * Nn * Dd;
static constexpr size_t OFF_BETA  = OFF_ALPHA + (size_t)Bb * Nn * Nn;

// Scratch (__device__ globals: no allocation allowed)
__device__ float g_Et[(size_t)Bb * Mm * Dd];     // E_t fp32 exact (for ec)
__device__ float g_EtR[(size_t)Bb * Mm * Dd];    // E_t pre-rounded to tf32 (for GEMM B)
__device__ float g_t1[Bb * Mm];
__device__ float g_t2[Bb * Mm];
__device__ float g_ecpart[Bb * 24 * Dd];
__device__ float g_scal[2 + 3 * Bb];

// ---------------------------------------------------------------------------
// Helpers (all plain sm_103-legal: mma.sync tf32, cp.async, cvt.rna.tf32)
// ---------------------------------------------------------------------------
__device__ __forceinline__ uint32_t smem_u32(const void* p) {
    uint32_t a;
    asm("{ .reg .u64 t; cvta.to.shared.u64 t, %1; cvt.u32.u64 %0, t; }" : "=r"(a) : "l"(p));
    return a;
}
__device__ __forceinline__ uint32_t f2tf(float x) {
    uint32_t r;
    asm("cvt.rna.tf32.f32 %0, %1;" : "=r"(r) : "f"(x));
    return r;
}
#define CP_ASYNC16(dst, src) asm volatile("cp.async.cg.shared.global [%0], [%1], 16;" :: "r"(dst), "l"(src))
#define CP_COMMIT()          asm volatile("cp.async.commit_group;" ::: "memory")
#define CP_WAIT(n)           asm volatile("cp.async.wait_group %0;" :: "n"(n) : "memory")

__device__ __forceinline__ void mma_tf32(float* d, const uint32_t* a, const uint32_t* b) {
    asm volatile(
        "mma.sync.aligned.m16n8k8.row.col.f32.tf32.tf32.f32 "
        "{%0,%1,%2,%3}, {%4,%5,%6,%7}, {%8,%9}, {%0,%1,%2,%3};"
        : "+f"(d[0]), "+f"(d[1]), "+f"(d[2]), "+f"(d[3])
        : "r"(a[0]), "r"(a[1]), "r"(a[2]), "r"(a[3]), "r"(b[0]), "r"(b[1]));
}

__device__ __forceinline__ float bredSum256(float v, float* sred) {
    #pragma unroll
    for (int o = 16; o; o >>= 1) v += __shfl_down_sync(0xffffffffu, v, o);
    __syncthreads();
    if ((threadIdx.x & 31) == 0) sred[threadIdx.x >> 5] = v;
    __syncthreads();
    float t = 0.f;
    #pragma unroll
    for (int k = 0; k < 8; k++) t += sred[k];
    return t;
}

__device__ __forceinline__ float exp_tanh(float x) {
    float ez = __expf(2.0f * x);
    float t  = 1.0f - __fdividef(2.0f, ez + 1.0f);
    return __expf(t);
}

// ---------------------------------------------------------------------------
// Kernel 1: E_t = link_features @ WE ; t1 = E_t.b1 ; t2 = E_t.b2 ; EtR = tf32(E_t)
// ---------------------------------------------------------------------------
__global__ __launch_bounds__(128) void k_et(const float* __restrict__ link,
                                            const float* __restrict__ Wmat,
                                            const float* __restrict__ bvec) {
    __shared__ float sWE[FEe][Dd];
    __shared__ float sLink[16][FEe];
    __shared__ float sP1[16][4];
    __shared__ float sP2[16][4];

    const int tid = threadIdx.x;
    const int rowBase = blockIdx.x * 16;

    for (int i = tid; i < FEe * Dd; i += 128) sWE[i >> 7][i & 127] = Wmat[i];
    for (int i = tid; i < 16 * FEe; i += 128) {
        int r = i >> 6, f = i & 63;
        sLink[r][f] = link[(size_t)(rowBase + r) * FEe + f];
    }
    __syncthreads();

    const float b1v = bvec[tid];
    const float b2v = bvec[Dd + tid];
    const int lane = tid & 31, warp = tid >> 5;

    #pragma unroll 1
    for (int r = 0; r < 16; r++) {
        float acc = 0.f;
        #pragma unroll
        for (int f = 0; f < FEe; f++) acc = fmaf(sLink[r][f], sWE[f][tid], acc);
        const size_t oi = (size_t)(rowBase + r) * Dd + tid;
        g_Et[oi]  = acc;
        g_EtR[oi] = __uint_as_float(f2tf(acc));
        float p1 = acc * b1v, p2 = acc * b2v;
        #pragma unroll
        for (int o = 16; o; o >>= 1) {
            p1 += __shfl_down_sync(0xffffffffu, p1, o);
            p2 += __shfl_down_sync(0xffffffffu, p2, o);
        }
        if (lane == 0) { sP1[r][warp] = p1; sP2[r][warp] = p2; }
    }
    __syncthreads();
    if (tid < 16) {
        g_t1[rowBase + tid] = sP1[tid][0] + sP1[tid][1] + sP1[tid][2] + sP1[tid][3];
        g_t2[rowBase + tid] = sP2[tid][0] + sP2[tid][1] + sP2[tid][2] + sP2[tid][3];
    }
}

// ---------------------------------------------------------------------------
// Kernel 2: deterministic partial column sums of E_t (for ec)
// ---------------------------------------------------------------------------
__global__ __launch_bounds__(128) void k_ec() {
    const int bx = blockIdx.x;
    const int b = bx / 24, seg = bx % 24;
    const int d = threadIdx.x;
    const float* p = g_Et + ((size_t)b * Mm + (size_t)seg * 128) * Dd + d;
    float acc = 0.f;
    #pragma unroll 4
    for (int m = 0; m < 128; m++) acc += p[(size_t)m * Dd];
    g_ecpart[(size_t)bx * Dd + d] = acc;
}

// ---------------------------------------------------------------------------
// Kernel 3: tiny scalar setup
// ---------------------------------------------------------------------------
__global__ __launch_bounds__(256) void k_scal(const float* __restrict__ bet,
                                              const float* __restrict__ WH,
                                              const float* __restrict__ av,
                                              const float* __restrict__ bv) {
    __shared__ float sred[8];
    const int tid = threadIdx.x;
    const float wh = (tid < Dd) ? WH[tid] : 0.f;
    float c1 = bredSum256(wh * ((tid < Dd) ? av[tid] : 0.f), sred);
    float c2 = bredSum256(wh * ((tid < Dd) ? av[Dd + tid] : 0.f), sred);
    if (tid == 0) { g_scal[0] = c1; g_scal[1] = c2; }

    const float invM = 1.0f / (float)Mm;
    for (int b = 0; b < Bb; b++) {
        float ecsum = 0.f;
        if (tid < Dd) {
            #pragma unroll
            for (int k = 0; k < 24; k++) ecsum += g_ecpart[(size_t)(b * 24 + k) * Dd + tid];
        }
        float ecv = ecsum * invM;
        float s3 = bredSum256(ecv * ((tid < Dd) ? av[2 * Dd + tid] : 0.f), sred);
        float h = 0.f;
        for (int i = tid; i < Nn; i += 256) h += bet[(size_t)b * Nn + i];
        float havg = bredSum256(h, sred) * (1.0f / (float)Nn);
        if (tid == 0) {
            g_scal[2 + b] = s3;
            float e0 = 0.f;
            for (int k = 0; k < 24; k++) e0 += g_ecpart[(size_t)(b * 24 + k) * Dd];
            g_scal[10 + b] = e0 * invM;
            g_scal[18 + b] = bv[2 * Dd] * havg;
        }
        __syncthreads();
    }
}

// ---------------------------------------------------------------------------
// Kernel 4: node attention (vectorized int4/float4)
// ---------------------------------------------------------------------------
__global__ __launch_bounds__(256) void k_node(const float* __restrict__ bet,
                                              const int* __restrict__ adj,
                                              const float* __restrict__ WH,
                                              float* __restrict__ out) {
    __shared__ float sb[Nn];
    __shared__ float sw[Nn];
    __shared__ float sred[8];

    const int row = blockIdx.x;
    const int b = row >> 11;
    const int i = row & (Nn - 1);
    const int tid = threadIdx.x;

    const float c1 = g_scal[0], c2 = g_scal[1];
    const float s3 = g_scal[2 + b], ec0 = g_scal[10 + b];

    const float* betb = bet + (size_t)b * Nn;
    for (int j = tid; j < Nn; j += 256) sb[j] = betb[j];
    __syncthreads();

    const float u = fmaf(sb[i], c1, s3);
    const int4* ar4 = (const int4*)(adj + (size_t)row * Nn);
    float4* sw4 = (float4*)sw;
    const float4* sb4 = (const float4*)sb;

    float lsum = 0.f;
    #pragma unroll
    for (int it = 0; it < 2; it++) {
        int j4 = tid + it * 256;
        int4 a4 = ar4[j4];
        float4 bq = sb4[j4];
        float4 w4;
        w4.x = (a4.x > 0) ? exp_tanh(fmaf(bq.x, c2, u)) : 0.f;
        w4.y = (a4.y > 0) ? exp_tanh(fmaf(bq.y, c2, u)) : 0.f;
        w4.z = (a4.z > 0) ? exp_tanh(fmaf(bq.z, c2, u)) : 0.f;
        w4.w = (a4.w > 0) ? exp_tanh(fmaf(bq.w, c2, u)) : 0.f;
        sw4[j4] = w4;
        lsum += (w4.x + w4.y) + (w4.z + w4.w);
    }
    float total = bredSum256(lsum, sred);
    const bool uni = !(total > 0.f);
    const float inv = uni ? 0.f : __fdividef(1.f, total);
    const float uval = 1.0f / (float)Nn;

    float4* alphar = (float4*)(out + OFF_ALPHA + (size_t)row * Nn);
    float sacc = 0.f;
    #pragma unroll
    for (int it = 0; it < 2; it++) {
        int j4 = tid + it * 256;
        float4 w4 = sw4[j4];
        float4 bq = sb4[j4];
        float4 a4;
        a4.x = uni ? uval : w4.x * inv;
        a4.y = uni ? uval : w4.y * inv;
        a4.z = uni ? uval : w4.z * inv;
        a4.w = uni ? uval : w4.w * inv;
        alphar[j4] = a4;
        sacc = fmaf(a4.x, bq.x, fmaf(a4.y, bq.y, fmaf(a4.z, bq.z, fmaf(a4.w, bq.w, sacc))));
    }
    float s = bredSum256(sacc, sred);

    if (tid < Dd) {
        float hv = s * WH[tid];
        out[OFF_H  + (size_t)row * Dd + tid] = hv;
        out[OFF_HM + (size_t)row * Dd + tid] = hv * ec0;
    }
}

// ---------------------------------------------------------------------------
// Kernel 5: edge attention softmax (vectorized)
// ---------------------------------------------------------------------------
__global__ __launch_bounds__(256) void k_edge(const int* __restrict__ adj,
                                              float* __restrict__ out) {
    __shared__ float st2[Mm];
    __shared__ float sw[Mm];
    __shared__ float sred[8];

    const int row = blockIdx.x;
    const int b = row / Mm;
    const int tid = threadIdx.x;

    const float gsh = g_scal[18 + b];
    const float* t2b = g_t2 + (size_t)b * Mm;
    for (int j = tid; j < Mm; j += 256) st2[j] = t2b[j];
    __syncthreads();

    const float u = g_t1[row] + gsh;
    const int4* ar4 = (const int4*)(adj + (size_t)row * Mm);
    float4* sw4 = (float4*)sw;
    const float4* st4 = (const float4*)st2;

    float lsum = 0.f;
    #pragma unroll
    for (int it = 0; it < 3; it++) {
        int j4 = tid + it * 256;
        int4 a4 = ar4[j4];
        float4 tq = st4[j4];
        float4 w4;
        w4.x = (a4.x > 0) ? exp_tanh(u + tq.x) : 0.f;
        w4.y = (a4.y > 0) ? exp_tanh(u + tq.y) : 0.f;
        w4.z = (a4.z > 0) ? exp_tanh(u + tq.z) : 0.f;
        w4.w = (a4.w > 0) ? exp_tanh(u + tq.w) : 0.f;
        sw4[j4] = w4;
        lsum += (w4.x + w4.y) + (w4.z + w4.w);
    }
    float total = bredSum256(lsum, sred);
    const bool uni = !(total > 0.f);
    const float inv = uni ? 0.f : __fdividef(1.f, total);
    const float uval = 1.0f / (float)Mm;

    float4* br = (float4*)(out + OFF_BETA + (size_t)row * Mm);
    #pragma unroll
    for (int it = 0; it < 3; it++) {
        int j4 = tid + it * 256;
        float4 w4 = sw4[j4];
        float4 o4;
        o4.x = uni ? uval : w4.x * inv;
        o4.y = uni ? uval : w4.y * inv;
        o4.z = uni ? uval : w4.z * inv;
        o4.w = uni ? uval : w4.w * inv;
        br[j4] = o4;
    }
}

// ---------------------------------------------------------------------------
// Kernel 6: E_new = beta @ E_t via mma.sync tf32 (plain sm_103 HMMA path)
// BM=64, BN=128 (=D), BK=32; 128 threads / 4 warps; warp tile 32x64.
// A = beta rows (row-major), B = EtR [k][d] (col-major k x n fragments).
// cp.async double-buffered. Grid = 8 batches x 48 tiles = 384 CTAs.
// ---------------------------------------------------------------------------
static constexpr int GA_F = 64 * 36;               // A stage floats (pad 36)
static constexpr int GB_F = 32 * 132;              // B stage floats (pad 132)
static constexpr int G_SMEM = (2 * GA_F + 2 * GB_F) * 4;   // 52224 B

__global__ __launch_bounds__(128) void k_gemm_mma(const float* __restrict__ beta_all,
                                                  float* __restrict__ Eout) {
    extern __shared__ float sm[];
    const uint32_t smb = smem_u32(sm);
    const int tid = threadIdx.x;
    const int wid = tid >> 5;
    const int lane = tid & 31;
    const int lr = lane >> 2;      // 0..7
    const int lc = lane & 3;       // 0..3

    const int bt = blockIdx.x;
    const int batch = bt / 48;
    const int rowBase = (bt % 48) * 64;

    const float* Ag = beta_all + (size_t)batch * Mm * Mm + (size_t)rowBase * Mm;
    const float* Bg = g_EtR + (size_t)batch * Mm * Dd;

    const int m0 = (wid & 1) * 32;   // warp row offset within 64
    const int n0 = (wid >> 1) * 64;  // warp col offset within 128

    float acc[2][8][4];
    #pragma unroll
    for (int mt = 0; mt < 2; mt++)
        #pragma unroll
        for (int nt = 0; nt < 8; nt++)
            #pragma unroll
            for (int q = 0; q < 4; q++) acc[mt][nt][q] = 0.f;

    // Async load of chunk c into stage s
    auto load_chunk = [&](int c, int s) {
        const uint32_t sa = smb + (s * GA_F) * 4;
        const uint32_t sbs = smb + (2 * GA_F + s * GB_F) * 4;
        #pragma unroll
        for (int t = 0; t < 4; t++) {
            int q = tid + t * 128;            // 0..511
            int row = q >> 3, k4 = q & 7;
            CP_ASYNC16(sa + (row * 36 + k4 * 4) * 4,
                       Ag + (size_t)row * Mm + c * 32 + k4 * 4);
        }
        #pragma unroll
        for (int t = 0; t < 8; t++) {
            int q = tid + t * 128;            // 0..1023
            int k = q >> 5, d4 = q & 31;
            CP_ASYNC16(sbs + (k * 132 + d4 * 4) * 4,
                       Bg + (size_t)(c * 32 + k) * Dd + d4 * 4);
        }
    };

    constexpr int NC = Mm / 32;   // 96 chunks
    load_chunk(0, 0);
    CP_COMMIT();

    #pragma unroll 1
    for (int c = 0; c < NC; c++) {
        const int s = c & 1;
        if (c + 1 < NC) {
            load_chunk(c + 1, (c + 1) & 1);
            CP_COMMIT();
            CP_WAIT(1);
        } else {
            CP_WAIT(0);
        }
        __syncthreads();

        const float* As = sm + s * GA_F;
        const float* Bs = sm + 2 * GA_F + s * GB_F;

        #pragma unroll
        for (int kk = 0; kk < 4; kk++) {
            const int k = kk * 8;
            uint32_t af[2][4];
            #pragma unroll
            for (int mt = 0; mt < 2; mt++) {
                const float* ap = As + (m0 + mt * 16 + lr) * 36 + k + lc;
                af[mt][0] = f2tf(ap[0]);
                af[mt][1] = f2tf(ap[8 * 36]);
                af[mt][2] = f2tf(ap[4]);
                af[mt][3] = f2tf(ap[8 * 36 + 4]);
            }
            uint32_t bf[8][2];
            const uint32_t* b0p = (const uint32_t*)(Bs + (k + lc) * 132 + n0 + lr);
            const uint32_t* b1p = (const uint32_t*)(Bs + (k + 4 + lc) * 132 + n0 + lr);
            #pragma unroll
            for (int nt = 0; nt < 8; nt++) {
                bf[nt][0] = b0p[nt * 8];
                bf[nt][1] = b1p[nt * 8];
            }
            #pragma unroll
            for (int mt = 0; mt < 2; mt++)
                #pragma unroll
                for (int nt = 0; nt < 8; nt++)
                    mma_tf32(acc[mt][nt], af[mt], bf[nt]);
        }
        __syncthreads();
    }

    // Epilogue: D[row, d]
    float* Cb = Eout + (size_t)batch * Mm * Dd;
    #pragma unroll
    for (int mt = 0; mt < 2; mt++) {
        #pragma unroll
        for (int nt = 0; nt < 8; nt++) {
            const int row = rowBase + m0 + mt * 16 + lr;
            const int col = n0 + nt * 8 + lc * 2;
            float2 v0 = make_float2(acc[mt][nt][0], acc[mt][nt][1]);
            float2 v1 = make_float2(acc[mt][nt][2], acc[mt][nt][3]);
            *(float2*)(Cb + (size_t)row * Dd + col) = v0;
            *(float2*)(Cb + (size_t)(row + 8) * Dd + col) = v1;
        }
    }
}

// ---------------------------------------------------------------------------
extern "C" void kernel_launch(void* const* d_in, const int* in_sizes, int n_in,
                              void* d_out, int out_size) {
    const float* bet  = (const float*)d_in[0];
    const float* link = (const float*)d_in[1];
    const int*   nadj = (const int*)d_in[2];
    const int*   eadj = (const int*)d_in[3];
    const float* WH   = (const float*)d_in[4];
    const float* WE   = (const float*)d_in[5];
    const float* av   = (const float*)d_in[6];
    const float* bv   = (const float*)d_in[7];
    float* out = (float*)d_out;

    cudaFuncSetAttribute(k_gemm_mma, cudaFuncAttributeMaxDynamicSharedMemorySize, G_SMEM);

    k_et  <<<Bb * Mm / 16, 128>>>(link, WE, bv);
    k_ec  <<<Bb * 24, 128>>>();
    k_scal<<<1, 256>>>(bet, WH, av, bv);
    k_node<<<Bb * Nn, 256>>>(bet, nadj, WH, out);
    k_edge<<<Bb * Mm, 256>>>(eadj, out);
    k_gemm_mma<<<48 * Bb, 128, G_SMEM>>>(out + OFF_BETA, out + OFF_E);
}